// round 6
// baseline (speedup 1.0000x reference)
#include <cuda_runtime.h>
#include <cstdint>

#define B_    16
#define T_    1024
#define V_    8192
#define H_    1024
#define NBLK  128
#define BTV   134217728   // B_*T_*V_

// ---------------------------------------------------------------------------
// Device-global scratch (allocation is forbidden) + grid-barrier state.
// g_hs layout: [t][j][b]  (j = hidden index). 64 MB.
// ---------------------------------------------------------------------------
__device__ float    g_hs[(size_t)T_ * B_ * H_];
__device__ unsigned g_bar_count = 0;
__device__ unsigned g_bar_sense = 0;

// ---------------------------------------------------------------------------
// Packed f32x2 helpers (FFMA2 is only reachable via PTX fma.rn.f32x2)
// ---------------------------------------------------------------------------
__device__ __forceinline__ unsigned long long pack2(float x, float y) {
    unsigned long long r;
    asm("mov.b64 %0, {%1, %2};" : "=l"(r) : "f"(x), "f"(y));
    return r;
}
__device__ __forceinline__ void fma2(unsigned long long &d,
                                     unsigned long long a,
                                     unsigned long long b) {
    asm("fma.rn.f32x2 %0, %1, %2, %0;" : "+l"(d) : "l"(a), "l"(b));
}
__device__ __forceinline__ void unpack2(unsigned long long v, float &lo, float &hi) {
    asm("mov.b64 {%0, %1}, %2;" : "=f"(lo), "=f"(hi) : "l"(v));
}

// ---------------------------------------------------------------------------
// Kernel 1: persistent RNN recurrence.
//   h_t[b][j] = tanh( Wx_w[j, x[b,t]] + Wx_b[j] + sum_k h_{t-1}[b][k]*Wh[j][k] )
// 128 blocks x 128 threads. Block bi owns j in [8*bi, 8*bi+8), all 16 b.
// Thread: j = j0 + (tid>>4), b = tid&15  (warp = 2 j x 16 b).
// Shared: h_s[1024][16] (h_{t-1}, [k][b], conflict-free reads) + wh_s[8][1024].
// One grid barrier per step (sense-reversing; safe across graph replays).
// ---------------------------------------------------------------------------
extern __shared__ float smem_dyn[];

__global__ void __launch_bounds__(128, 1)
rnn_recurrence_kernel(const int*   __restrict__ x,
                      const float* __restrict__ h0,
                      const float* __restrict__ Wx,
                      const float* __restrict__ Wxb,
                      const float* __restrict__ Wh,
                      float*       __restrict__ out,
                      int out_size)
{
    float* h_s  = smem_dyn;            // 16384 floats: h_{t-1} as [k][b]
    float* wh_s = smem_dyn + 16384;    //  8192 floats: Wh rows [jl][k]

    const int tid = threadIdx.x;
    const int j0  = (int)blockIdx.x * 8;
    const int jl  = tid >> 4;          // 0..7
    const int j   = j0 + jl;
    const int b   = tid & 15;

    // One-time: stage this block's 8 Wh rows into shared (32 KB).
    {
        const float4* src = (const float4*)(Wh + (size_t)j0 * H_);
        float4*       dst = (float4*)wh_s;
        #pragma unroll
        for (int s = 0; s < 16; s++)
            dst[tid + s * 128] = src[tid + s * 128];
    }

    const float  wxb   = Wxb[j];
    const float* wxrow = Wx + (size_t)j * V_;   // Wx_w row j: [V_] entries
    const int*   xrow  = x + b * T_;
    const float* whs   = wh_s + jl * H_;
    float*       hout  = g_hs + (size_t)j * 16 + b;

    for (int t = 0; t < T_; t++) {
        // ---- stage h_{t-1} into shared as [k][b] ----
        if (t == 0) {
            // h0 is [b][k]; transpose-gather (one-time cost)
            for (int i = tid; i < B_ * H_; i += 128)
                h_s[i] = h0[(i & 15) * H_ + (i >> 4)];
        } else {
            const float4* src = (const float4*)(g_hs + (size_t)(t - 1) * (B_ * H_));
            float4*       dst = (float4*)h_s;
            #pragma unroll
            for (int s = 0; s < 32; s++)
                dst[tid + s * 128] = __ldcg(src + tid + s * 128);
        }
        __syncthreads();

        // ---- embedding gather (L2-resident Wx, 32 MB) ----
        int   xi = __ldg(xrow + t);
        float e  = __ldg(wxrow + xi) + wxb;

        // ---- dot(h_{t-1}[b][:], Wh[j][:]) with 8 accumulator chains ----
        float a0 = 0.f, a1 = 0.f, a2 = 0.f, a3 = 0.f;
        float a4 = 0.f, a5 = 0.f, a6 = 0.f, a7 = 0.f;
        #pragma unroll 4
        for (int k = 0; k < H_; k += 8) {
            float4 w0 = *(const float4*)(whs + k);
            float4 w1 = *(const float4*)(whs + k + 4);
            a0 += w0.x * h_s[(k + 0) * 16 + b];
            a1 += w0.y * h_s[(k + 1) * 16 + b];
            a2 += w0.z * h_s[(k + 2) * 16 + b];
            a3 += w0.w * h_s[(k + 3) * 16 + b];
            a4 += w1.x * h_s[(k + 4) * 16 + b];
            a5 += w1.y * h_s[(k + 5) * 16 + b];
            a6 += w1.z * h_s[(k + 6) * 16 + b];
            a7 += w1.w * h_s[(k + 7) * 16 + b];
        }
        float dot = ((a0 + a1) + (a2 + a3)) + ((a4 + a5) + (a6 + a7));
        float hv  = tanhf(e + dot);

        // coalesced store: address j0*16 + tid
        __stcg(hout + (size_t)t * (B_ * H_), hv);

        if (t == T_ - 1 && out_size >= BTV + B_ * H_)
            out[(size_t)BTV + b * H_ + j] = hv;   // h_final [B][H]

        // ---- grid barrier (sense-reversing, replay-safe) ----
        __threadfence();
        __syncthreads();
        if (tid == 0) {
            unsigned gen = *((volatile unsigned*)&g_bar_sense);
            unsigned arr = atomicAdd(&g_bar_count, 1u);
            if (arr == NBLK - 1) {
                atomicExch(&g_bar_count, 0u);
                __threadfence();
                atomicAdd(&g_bar_sense, 1u);
            } else {
                while (*((volatile unsigned*)&g_bar_sense) == gen) { }
            }
        }
        __syncthreads();
        __threadfence();   // acquire: g_hs[t] writes from other blocks visible
    }
}

// ---------------------------------------------------------------------------
// Kernel 2: output GEMM.
//   logits[b][t][v] = sum_k hs[t][b][k] * Wy[v][k] + Wyb[v]
// A[m][k] = g_hs[t][k][b] with m = t*16+b (tile rows = 8 t x 16 b, so the
// A-tile is 8 contiguous 1 KB chunks in gmem). B[n][k] = Wy. 128x128x16
// tiles, 256 threads, 8x8 register micro-tiles on packed f32x2 FFMA2.
// ---------------------------------------------------------------------------
#define BK   16
#define LDAS 132   // 128 + pad 4: float4-aligned rows

__global__ void __launch_bounds__(256)
gemm_logits_kernel(const float* __restrict__ Wy,
                   const float* __restrict__ Wyb,
                   float*       __restrict__ out)
{
    __shared__ float As[BK][LDAS];
    __shared__ float Bs[BK][LDAS];

    const int tid = threadIdx.x;
    const int tx  = tid & 15;            // n micro-tile (8 cols)
    const int ty  = tid >> 4;            // m micro-tile (8 rows)
    const int n0  = (int)blockIdx.x * 128;
    const int t0  = (int)blockIdx.y * 8; // 8 t-rows -> m0 = t0*16

    // A loader: element e0 = tid*8 of the 2048-float tile, 2 x float4
    const int a_t = tid >> 5;                    // t_local 0..7
    const int a_k = (tid & 31) >> 1;             // k_local 0..15
    const int a_b = (tid & 1) * 8;               // b 0 or 8
    const float* Ag = g_hs + (size_t)(t0 + a_t) * (B_ * H_) + a_k * 16 + a_b;

    // B loader: row n = tid>>1, k-offset (tid&1)*8, 2 x float4
    const int b_n = tid >> 1;
    const int b_k = (tid & 1) * 8;
    const float* Bg = Wy + (size_t)(n0 + b_n) * H_ + b_k;

    unsigned long long acc[8][4];
    #pragma unroll
    for (int i = 0; i < 8; i++)
        #pragma unroll
        for (int jj = 0; jj < 4; jj++) acc[i][jj] = 0ull;

    for (int k0 = 0; k0 < H_; k0 += BK) {
        // prefetch before the sync so gmem latency overlaps the barrier
        float4 av0 = __ldg((const float4*)(Ag + (size_t)k0 * 16));
        float4 av1 = __ldg((const float4*)(Ag + (size_t)k0 * 16 + 4));
        float4 bv0 = __ldg((const float4*)(Bg + k0));
        float4 bv1 = __ldg((const float4*)(Bg + k0 + 4));
        __syncthreads();   // protect previous tile's reads
        *(float4*)&As[a_k][a_t * 16 + a_b]     = av0;
        *(float4*)&As[a_k][a_t * 16 + a_b + 4] = av1;
        Bs[b_k + 0][b_n] = bv0.x;  Bs[b_k + 1][b_n] = bv0.y;
        Bs[b_k + 2][b_n] = bv0.z;  Bs[b_k + 3][b_n] = bv0.w;
        Bs[b_k + 4][b_n] = bv1.x;  Bs[b_k + 5][b_n] = bv1.y;
        Bs[b_k + 6][b_n] = bv1.z;  Bs[b_k + 7][b_n] = bv1.w;
        __syncthreads();

        #pragma unroll
        for (int k = 0; k < BK; k++) {
            float4 aq0 = *(const float4*)&As[k][ty * 8];
            float4 aq1 = *(const float4*)&As[k][ty * 8 + 4];
            float4 bq0 = *(const float4*)&Bs[k][tx * 8];
            float4 bq1 = *(const float4*)&Bs[k][tx * 8 + 4];
            unsigned long long b2[4];
            b2[0] = pack2(bq0.x, bq0.y);  b2[1] = pack2(bq0.z, bq0.w);
            b2[2] = pack2(bq1.x, bq1.y);  b2[3] = pack2(bq1.z, bq1.w);
            float am[8] = {aq0.x, aq0.y, aq0.z, aq0.w,
                           aq1.x, aq1.y, aq1.z, aq1.w};
            #pragma unroll
            for (int i = 0; i < 8; i++) {
                unsigned long long a2 = pack2(am[i], am[i]);
                #pragma unroll
                for (int jj = 0; jj < 4; jj++) fma2(acc[i][jj], a2, b2[jj]);
            }
        }
    }

    // ---- epilogue: add bias, scatter to logits [b][t][v] ----
    float bias[8];
    #pragma unroll
    for (int jj = 0; jj < 8; jj++) bias[jj] = __ldg(Wyb + n0 + tx * 8 + jj);
    #pragma unroll
    for (int i = 0; i < 8; i++) {
        int m  = t0 * 16 + ty * 8 + i;
        int tt = m >> 4;
        int bb = m & 15;
        float* orow = out + ((size_t)bb * T_ + tt) * V_ + n0 + tx * 8;
        #pragma unroll
        for (int jj = 0; jj < 4; jj++) {
            float lo, hi;
            unpack2(acc[i][jj], lo, hi);
            float2 v = make_float2(lo + bias[jj * 2], hi + bias[jj * 2 + 1]);
            *(float2*)(orow + jj * 2) = v;
        }
    }
}

// ---------------------------------------------------------------------------
// Launch
// ---------------------------------------------------------------------------
extern "C" void kernel_launch(void* const* d_in, const int* in_sizes, int n_in,
                              void* d_out, int out_size) {
    const int*   x   = (const int*)  d_in[0];   // [B,T] int32
    const float* h0  = (const float*)d_in[1];   // [B,H]
    const float* Wx  = (const float*)d_in[2];   // [H,V]
    const float* Wxb = (const float*)d_in[3];   // [H]
    const float* Wh  = (const float*)d_in[4];   // [H,H]
    const float* Wy  = (const float*)d_in[5];   // [V,H]
    const float* Wyb = (const float*)d_in[6];   // [V]
    float* out = (float*)d_out;

    const int smem = (B_ * H_ + 8 * H_) * (int)sizeof(float);  // 96 KB
    cudaFuncSetAttribute(rnn_recurrence_kernel,
                         cudaFuncAttributeMaxDynamicSharedMemorySize, smem);

    rnn_recurrence_kernel<<<NBLK, 128, smem>>>(x, h0, Wx, Wxb, Wh, out, out_size);

    dim3 grid(V_ / 128, (T_ * B_) / 128);   // (64, 128)
    gemm_logits_kernel<<<grid, 256>>>(Wy, Wyb, out);
}